// round 5
// baseline (speedup 1.0000x reference)
#include <cuda_runtime.h>
#include <cstdint>

// ---------------------------------------------------------------------------
// GraphConvLayer fused pipeline (TF32 tensor-core GEMM)
//   1) gather_kernel x5 : neighbor atom-sum -> g_Asum, bond-sum -> g_Bsum
//   2) gemm_kernel   x5 : [af | Asum] @ [W_self ; W_deg_top]  (K=512, TF32 mma)
//                         + bias + Bsum@W_deg_bot, ReLU -> g_pre
//   3) stats_kernel     : per-column sum / sumsq partials (deterministic)
//   4) finalize_kernel  : batchnorm scale/shift
//   5) norm_kernel      : g_pre -> d_out
// ---------------------------------------------------------------------------

#define NATOMS_MAX 200000

__device__ float g_Asum[(size_t)NATOMS_MAX * 256];
__device__ float g_Bsum[(size_t)NATOMS_MAX * 8];
__device__ float g_pre [(size_t)NATOMS_MAX * 256];
__device__ float g_part[2 * 256 * 256];   // [0:65536) sums, [65536:131072) sumsq
__device__ float g_scale[256];
__device__ float g_shift[256];

__device__ __forceinline__ uint32_t f2tf(float f) {
    uint32_t u;
    asm("cvt.rna.tf32.f32 %0, %1;" : "=r"(u) : "f"(f));
    return u;
}

__device__ __forceinline__ void mma_tf32(float* c, const uint32_t* a,
                                         uint32_t b0, uint32_t b1) {
    asm volatile(
        "mma.sync.aligned.m16n8k8.row.col.f32.tf32.tf32.f32 "
        "{%0,%1,%2,%3}, {%4,%5,%6,%7}, {%8,%9}, {%0,%1,%2,%3};"
        : "+f"(c[0]), "+f"(c[1]), "+f"(c[2]), "+f"(c[3])
        : "r"(a[0]), "r"(a[1]), "r"(a[2]), "r"(a[3]), "r"(b0), "r"(b1));
}

// ---------------------------------------------------------------------------
// 1) Gather: one 256-thread block per atom of this degree segment.
//    thread t accumulates column t of the neighbor atom rows.
// ---------------------------------------------------------------------------
__global__ void __launch_bounds__(256) gather_kernel(
    const float* __restrict__ af, const float* __restrict__ bf,
    const int* __restrict__ anbr, const int* __restrict__ bnbr,
    int d, int row_start)
{
    __shared__ int sa[8];
    __shared__ int sb[8];
    const int b = blockIdx.x, t = threadIdx.x;
    if (t < d)            sa[t]     = anbr[b * d + t];
    else if (t < 2 * d)   sb[t - d] = bnbr[b * d + (t - d)];
    __syncthreads();

    const size_t row = (size_t)(row_start + b);
    float acc = 0.f;
    for (int s = 0; s < d; ++s)
        acc += __ldg(af + (size_t)sa[s] * 256 + t);
    g_Asum[row * 256 + t] = acc;

    if (t < 8) {
        float v = 0.f;
        if (t < 6)
            for (int s = 0; s < d; ++s)
                v += __ldg(bf + (size_t)sb[s] * 6 + t);
        g_Bsum[row * 8 + t] = v;
    }
}

// ---------------------------------------------------------------------------
// 2) GEMM per degree segment: 128x128 CTA tile, K=512 in 16 steps of 32.
//    A rows come from atom_features (k<256) or g_Asum (k>=256).
//    B rows come from W_self (k<256) or W_deg rows 0..255 (k>=256).
//    8 warps = 4(M) x 2(N); warp tile 32x64; m16n8k8 TF32 mma.
// ---------------------------------------------------------------------------
__global__ void __launch_bounds__(256) gemm_kernel(
    const float* __restrict__ af,
    const float* __restrict__ Wself,     // [256,256] (in,out)
    const float* __restrict__ Wdeg,      // [262,256]
    const float* __restrict__ bias,      // [256]
    int row_start, int n_rows)
{
    __shared__ uint32_t sA[128][36];     // [m][k], pad 4 -> conflict-free frags
    __shared__ uint32_t sB[32][136];     // [k][n], pad 8 -> conflict-free frags
    __shared__ float s_wbot[6][128];
    __shared__ float s_bias[128];

    const int tid  = threadIdx.x;
    const int warp = tid >> 5, lane = tid & 31;
    const int m0 = blockIdx.x * 128;
    const int n0 = blockIdx.y * 128;
    const int wm = (warp & 3) * 32;
    const int wn = (warp >> 2) * 64;

    float acc[2][8][4];
#pragma unroll
    for (int i = 0; i < 2; ++i)
#pragma unroll
        for (int j = 0; j < 8; ++j)
#pragma unroll
            for (int k = 0; k < 4; ++k) acc[i][j][k] = 0.f;

    if (tid < 128) s_bias[tid] = bias[n0 + tid];
    for (int i = tid; i < 6 * 128; i += 256) {
        int j = i >> 7, c = i & 127;
        s_wbot[j][c] = Wdeg[(size_t)(256 + j) * 256 + n0 + c];
    }

    for (int kt = 0; kt < 16; ++kt) {
        const int k0 = kt * 32;
        // ---- load A tile 128x32 ----
        const float* Ab = (k0 < 256) ? af : g_Asum;
        const int kk = k0 & 255;
#pragma unroll
        for (int i = 0; i < 4; ++i) {
            int r = (tid >> 3) + i * 32;
            float4 v = make_float4(0.f, 0.f, 0.f, 0.f);
            if (m0 + r < n_rows)
                v = *(const float4*)(Ab + (size_t)(row_start + m0 + r) * 256
                                        + kk + (tid & 7) * 4);
            uint32_t* dst = &sA[r][(tid & 7) * 4];
            dst[0] = f2tf(v.x); dst[1] = f2tf(v.y);
            dst[2] = f2tf(v.z); dst[3] = f2tf(v.w);
        }
        // ---- load B tile 32x128 ----
        const float* Bb = (k0 < 256) ? (Wself + (size_t)k0 * 256)
                                     : (Wdeg + (size_t)(k0 - 256) * 256);
#pragma unroll
        for (int i = 0; i < 4; ++i) {
            int idx = tid + i * 256;
            int k = idx >> 5, n4 = idx & 31;
            float4 v = *(const float4*)(Bb + (size_t)k * 256 + n0 + n4 * 4);
            uint32_t* dst = &sB[k][n4 * 4];
            dst[0] = f2tf(v.x); dst[1] = f2tf(v.y);
            dst[2] = f2tf(v.z); dst[3] = f2tf(v.w);
        }
        __syncthreads();

#pragma unroll
        for (int k8 = 0; k8 < 4; ++k8) {
            const int kb = k8 * 8 + (lane & 3);
            uint32_t afr[2][4];
#pragma unroll
            for (int mi = 0; mi < 2; ++mi) {
                int r = wm + mi * 16 + (lane >> 2);
                afr[mi][0] = sA[r    ][kb];
                afr[mi][1] = sA[r + 8][kb];
                afr[mi][2] = sA[r    ][kb + 4];
                afr[mi][3] = sA[r + 8][kb + 4];
            }
#pragma unroll
            for (int ni = 0; ni < 8; ++ni) {
                int c = wn + ni * 8 + (lane >> 2);
                uint32_t b0 = sB[kb][c], b1 = sB[kb + 4][c];
                mma_tf32(acc[0][ni], afr[0], b0, b1);
                mma_tf32(acc[1][ni], afr[1], b0, b1);
            }
        }
        __syncthreads();
    }

    // ---- epilogue: + bias + Bsum@W_deg_bot, ReLU, store g_pre ----
#pragma unroll
    for (int mi = 0; mi < 2; ++mi) {
#pragma unroll
        for (int half = 0; half < 2; ++half) {
            int r = wm + mi * 16 + (lane >> 2) + half * 8;
            if (m0 + r >= n_rows) continue;
            size_t grow = (size_t)(row_start + m0 + r);
            float4 b03 = *(const float4*)(g_Bsum + grow * 8);
            float4 b47 = *(const float4*)(g_Bsum + grow * 8 + 4);
            float bs[6] = {b03.x, b03.y, b03.z, b03.w, b47.x, b47.y};
#pragma unroll
            for (int ni = 0; ni < 8; ++ni) {
                int cl = wn + ni * 8 + (lane & 3) * 2;
                float v0 = acc[mi][ni][half * 2 + 0] + s_bias[cl];
                float v1 = acc[mi][ni][half * 2 + 1] + s_bias[cl + 1];
#pragma unroll
                for (int j = 0; j < 6; ++j) {
                    v0 = fmaf(bs[j], s_wbot[j][cl],     v0);
                    v1 = fmaf(bs[j], s_wbot[j][cl + 1], v1);
                }
                v0 = fmaxf(v0, 0.f);
                v1 = fmaxf(v1, 0.f);
                *(float2*)(g_pre + grow * 256 + n0 + cl) = make_float2(v0, v1);
            }
        }
    }
}

// ---------------------------------------------------------------------------
// 3) per-column partial sum / sumsq (deterministic, no atomics)
// ---------------------------------------------------------------------------
__global__ void __launch_bounds__(256) stats_kernel(int n_atoms)
{
    const int p = blockIdx.x, t = threadIdx.x;
    const int chunk = (n_atoms + 255) >> 8;
    int r0 = p * chunk;
    int r1 = r0 + chunk; if (r1 > n_atoms) r1 = n_atoms;
    float s = 0.f, s2 = 0.f;
    for (int r = r0; r < r1; ++r) {
        float v = g_pre[(size_t)r * 256 + t];
        s += v;
        s2 = fmaf(v, v, s2);
    }
    g_part[p * 256 + t] = s;
    g_part[65536 + p * 256 + t] = s2;
}

__global__ void finalize_kernel(const float* __restrict__ bnw,
                                const float* __restrict__ bnb, int n_atoms)
{
    const int t = threadIdx.x;
    float s = 0.f, s2 = 0.f;
    for (int p = 0; p < 256; ++p) {
        s  += g_part[p * 256 + t];
        s2 += g_part[65536 + p * 256 + t];
    }
    const float inv = 1.f / (float)n_atoms;
    const float mean = s * inv;
    const float var  = s2 * inv - mean * mean;
    const float a = bnw[t] * rsqrtf(var + 1e-5f);
    g_scale[t] = a;
    g_shift[t] = bnb[t] - mean * a;
}

// ---------------------------------------------------------------------------
// 5) normalize: out = pre * scale[c] + shift[c]
// ---------------------------------------------------------------------------
__global__ void __launch_bounds__(256) norm_kernel(float* __restrict__ out,
                                                   int total4)
{
    __shared__ float sc[256], sh[256];
    sc[threadIdx.x] = g_scale[threadIdx.x];
    sh[threadIdx.x] = g_shift[threadIdx.x];
    __syncthreads();
    for (int i = blockIdx.x * blockDim.x + threadIdx.x; i < total4;
         i += gridDim.x * blockDim.x) {
        float4 v = *(const float4*)(g_pre + (size_t)i * 4);
        int c = (i & 63) * 4;
        v.x = fmaf(v.x, sc[c],     sh[c]);
        v.y = fmaf(v.y, sc[c + 1], sh[c + 1]);
        v.z = fmaf(v.z, sc[c + 2], sh[c + 2]);
        v.w = fmaf(v.w, sc[c + 3], sh[c + 3]);
        *(float4*)(out + (size_t)i * 4) = v;
    }
}

// ---------------------------------------------------------------------------
extern "C" void kernel_launch(void* const* d_in, const int* in_sizes, int n_in,
                              void* d_out, int out_size)
{
    const float* af = (const float*)d_in[0];
    const float* bf = (const float*)d_in[1];

    // Detect input ordering of the 10 neighbor arrays:
    //  interleaved: a1,b1,a2,b2,...  (setup_inputs dict order) -> sizes[3]==sizes[2]
    //  grouped:     a1..a5,b1..b5    (reference signature order)
    int a_idx[5], b_idx[5];
    const bool interleaved = (in_sizes[3] == in_sizes[2]);
    for (int d = 0; d < 5; ++d) {
        if (interleaved) { a_idx[d] = 2 + 2 * d; b_idx[d] = 3 + 2 * d; }
        else             { a_idx[d] = 2 + d;     b_idx[d] = 7 + d;     }
    }

    const float* Wself = (const float*)d_in[12];
    const float* bias  = (const float*)d_in[13];
    const float* Wdeg[5];
    for (int d = 0; d < 5; ++d) Wdeg[d] = (const float*)d_in[14 + d];
    const float* bnw = (const float*)d_in[19];
    const float* bnb = (const float*)d_in[20];

    const int n_atoms = in_sizes[0] / 256;

    int nd[5], off[5], o = 0;
    for (int d = 0; d < 5; ++d) {
        nd[d]  = in_sizes[a_idx[d]] / (d + 1);
        off[d] = o;
        o += nd[d];
    }

    // 1) gather
    for (int d = 0; d < 5; ++d) {
        if (nd[d] > 0)
            gather_kernel<<<nd[d], 256>>>(af, bf,
                                          (const int*)d_in[a_idx[d]],
                                          (const int*)d_in[b_idx[d]],
                                          d + 1, off[d]);
    }
    // 2) GEMM per degree segment
    for (int d = 0; d < 5; ++d) {
        if (nd[d] > 0) {
            dim3 grid((nd[d] + 127) / 128, 2);
            gemm_kernel<<<grid, 256>>>(af, Wself, Wdeg[d], bias, off[d], nd[d]);
        }
    }
    // 3,4) batchnorm statistics
    stats_kernel<<<256, 256>>>(n_atoms);
    finalize_kernel<<<1, 256>>>(bnw, bnb, n_atoms);
    // 5) normalize
    const int total4 = n_atoms * 64;
    norm_kernel<<<1184, 256>>>((float*)d_out, total4);
}

// round 7
// speedup vs baseline: 1.9435x; 1.9435x over previous
#include <cuda_runtime.h>
#include <cstdint>

// ---------------------------------------------------------------------------
// GraphConvLayer — optimized mma.sync tf32 pipeline (compute_103-safe)
//   0) prep_kernel      : transpose weights -> tf32 [n][k] copies
//   1) gather_atoms<D>  : neighbor atom-sum -> g_Asum (tf32-rounded, float4)
//      gather_bonds<D>  : neighbor bond-sum -> g_Bsum (fp32)
//   2) gemm_mma         : 128x256x512 CTA tiles, cp.async double-buffer,
//                         ldmatrix-b16 tf32 fragments, m16n8k8 mma,
//                         fp32 bias+bond epilogue + ReLU -> g_pre
//   3) stats / finalize : deterministic batchnorm stats (float4)
//   4) norm_kernel      : g_pre -> d_out
// ---------------------------------------------------------------------------

#define NATOMS_MAX 200000

__device__ float g_Asum[(size_t)NATOMS_MAX * 256];
__device__ float g_Bsum[(size_t)NATOMS_MAX * 8];
__device__ float g_pre [(size_t)NATOMS_MAX * 256];
__device__ float g_Wt_self[256 * 256];        // [n][k], tf32-rounded
__device__ float g_Wt_deg [5 * 256 * 256];    // [d][n][k]
__device__ float g_part[2 * 256 * 256];
__device__ float g_scale[256];
__device__ float g_shift[256];

// ---------------- helpers ----------------
__device__ __forceinline__ uint32_t smem_u32(const void* p) {
    uint32_t a;
    asm("{ .reg .u64 t; cvta.to.shared.u64 t, %1; cvt.u32.u64 %0, t; }"
        : "=r"(a) : "l"(p));
    return a;
}
__device__ __forceinline__ uint32_t f2tf(float f) {
    uint32_t u;
    asm("cvt.rna.tf32.f32 %0, %1;" : "=r"(u) : "f"(f));
    return u;
}
__device__ __forceinline__ void cp_async16(uint32_t saddr, const void* gptr) {
    size_t g = __cvta_generic_to_global(gptr);
    asm volatile("cp.async.cg.shared.global [%0], [%1], 16;"
                 :: "r"(saddr), "l"(g));
}
#define CP_COMMIT() asm volatile("cp.async.commit_group;" ::: "memory")
#define CP_WAIT1()  asm volatile("cp.async.wait_group 1;" ::: "memory")

__device__ __forceinline__ void ldm_x4(uint32_t* r, uint32_t addr) {
    asm volatile("ldmatrix.sync.aligned.m8n8.x4.shared.b16 {%0,%1,%2,%3}, [%4];"
                 : "=r"(r[0]), "=r"(r[1]), "=r"(r[2]), "=r"(r[3]) : "r"(addr));
}
__device__ __forceinline__ void mma_tf32(float* c, const uint32_t* a,
                                         uint32_t b0, uint32_t b1) {
    asm volatile(
        "mma.sync.aligned.m16n8k8.row.col.f32.tf32.tf32.f32 "
        "{%0,%1,%2,%3}, {%4,%5,%6,%7}, {%8,%9}, {%0,%1,%2,%3};"
        : "+f"(c[0]), "+f"(c[1]), "+f"(c[2]), "+f"(c[3])
        : "r"(a[0]), "r"(a[1]), "r"(a[2]), "r"(a[3]), "r"(b0), "r"(b1));
}

// ---------------------------------------------------------------------------
// 0) prep: Wt[n][k] = tf32(W[k][n])
// ---------------------------------------------------------------------------
__global__ void __launch_bounds__(256) prep_kernel(
    const float* __restrict__ Ws,
    const float* __restrict__ W1, const float* __restrict__ W2,
    const float* __restrict__ W3, const float* __restrict__ W4,
    const float* __restrict__ W5)
{
    const float* Wd[5] = {W1, W2, W3, W4, W5};
    int id = blockIdx.x * 256 + threadIdx.x;
    if (id < 65536) {
        int n = id >> 8, k = id & 255;
        g_Wt_self[id] = __uint_as_float(f2tf(__ldg(Ws + k * 256 + n)));
    } else if (id < 6 * 65536) {
        int t = id - 65536;
        int d = t >> 16, rr = t & 65535;
        int n = rr >> 8, k = rr & 255;
        g_Wt_deg[t] = __uint_as_float(f2tf(__ldg(Wd[d] + k * 256 + n)));
    }
}

// ---------------------------------------------------------------------------
// 1) gathers
// ---------------------------------------------------------------------------
template <int D>
__global__ void __launch_bounds__(256) gather_atoms(
    const float* __restrict__ af, const int* __restrict__ anbr,
    int row_start, int n)
{
    int gid = blockIdx.x * 256 + threadIdx.x;
    int atom = gid >> 6;
    if (atom >= n) return;
    int c = gid & 63;
    int idx[D];
#pragma unroll
    for (int s = 0; s < D; ++s) idx[s] = __ldg(anbr + atom * D + s);
    float4 acc = make_float4(0.f, 0.f, 0.f, 0.f);
#pragma unroll
    for (int s = 0; s < D; ++s) {
        float4 v = __ldg((const float4*)af + (size_t)idx[s] * 64 + c);
        acc.x += v.x; acc.y += v.y; acc.z += v.z; acc.w += v.w;
    }
    acc.x = __uint_as_float(f2tf(acc.x));
    acc.y = __uint_as_float(f2tf(acc.y));
    acc.z = __uint_as_float(f2tf(acc.z));
    acc.w = __uint_as_float(f2tf(acc.w));
    ((float4*)g_Asum)[(size_t)(row_start + atom) * 64 + c] = acc;
}

template <int D>
__global__ void __launch_bounds__(256) gather_bonds(
    const float* __restrict__ bf, const int* __restrict__ bnbr,
    int row_start, int n)
{
    int atom = blockIdx.x * 256 + threadIdx.x;
    if (atom >= n) return;
    float s[6] = {0.f, 0.f, 0.f, 0.f, 0.f, 0.f};
#pragma unroll
    for (int j = 0; j < D; ++j) {
        int idx = __ldg(bnbr + atom * D + j);
        const float* row = bf + (size_t)idx * 6;
#pragma unroll
        for (int q = 0; q < 6; ++q) s[q] += __ldg(row + q);
    }
    float* o = g_Bsum + (size_t)(row_start + atom) * 8;
    *(float4*)o       = make_float4(s[0], s[1], s[2], s[3]);
    *(float4*)(o + 4) = make_float4(s[4], s[5], 0.f, 0.f);
}

// ---------------------------------------------------------------------------
// 2) GEMM: CTA 128(M) x 256(N), K=512 in 16 stages of 32 (cp.async x2 buf).
//    8 warps: 2(M) x 4(N); warp tile 64x64; m16n8k8 tf32 mma.
//    smem tiles: A [128][32]f, B(n-major) [256][32]f, 128B rows, SW128 XOR.
// ---------------------------------------------------------------------------
__device__ __forceinline__ void issue_stage(
    uint32_t uA, uint32_t uB, int stage, int kt,
    const float* __restrict__ af, const float* __restrict__ WtD,
    int tid, int m0, int row_start, int n_rows)
{
    const int lrow = tid >> 3;          // 0..31
    const int lchk = tid & 7;           // 16B chunk within 128B row
    const int kk = (kt * 32) & 255;

    // A tile: 128 rows x 32 floats
    const float* Ab = (kt < 8) ? af : g_Asum;
    uint32_t dA = uA + stage * 16384;
#pragma unroll
    for (int p = 0; p < 4; ++p) {
        int r = lrow + p * 32;
        int rg = m0 + r; if (rg >= n_rows) rg = n_rows - 1;
        const char* src = (const char*)(Ab + (size_t)(row_start + rg) * 256 + kk)
                          + lchk * 16;
        cp_async16(dA + (uint32_t)r * 128 + (uint32_t)((lchk ^ (r & 7)) << 4), src);
    }
    // B tile: 256 n-rows x 32 floats (weights pre-transposed [n][k])
    const float* Bb = (kt < 8) ? g_Wt_self : WtD;
    uint32_t dB = uB + stage * 32768;
#pragma unroll
    for (int p = 0; p < 8; ++p) {
        int r = lrow + p * 32;
        const char* src = (const char*)(Bb + (size_t)r * 256 + kk) + lchk * 16;
        cp_async16(dB + (uint32_t)r * 128 + (uint32_t)((lchk ^ (r & 7)) << 4), src);
    }
}

__global__ void __launch_bounds__(256) gemm_mma(
    const float* __restrict__ af,
    const float* __restrict__ Wdeg_orig,   // original [262][256] for bond rows
    const float* __restrict__ bias,
    int deg, int row_start, int n_rows)
{
    extern __shared__ float dsm[];          // A: 2*4096 f, B: 2*8192 f
    __shared__ float s_wbot[6][256];
    __shared__ float s_bias[256];

    const uint32_t uA = smem_u32(dsm);
    const uint32_t uB = uA + 32768;

    const int tid = threadIdx.x;
    const int warp = tid >> 5, lane = tid & 31;
    const int m0 = blockIdx.x * 128;
    const int wm = (warp & 1) * 64;
    const int wn = (warp >> 1) * 64;
    const float* __restrict__ WtD = g_Wt_deg + (size_t)deg * 65536;

    s_bias[tid] = __ldg(bias + tid);
#pragma unroll
    for (int j = 0; j < 6; ++j)
        if ((tid >> 8) == 0)   // all 256 threads, one row each pass
            s_wbot[j][tid] = __ldg(Wdeg_orig + (size_t)(256 + j) * 256 + tid);

    float acc[4][8][4];
#pragma unroll
    for (int a = 0; a < 4; ++a)
#pragma unroll
        for (int b = 0; b < 8; ++b)
#pragma unroll
            for (int e = 0; e < 4; ++e) acc[a][b][e] = 0.f;

    // fragment addresses (ldmatrix b16 trick for tf32)
    const int jj = lane >> 3, rr = lane & 7;
    uint32_t rowA[4], rowB[4];
#pragma unroll
    for (int mt = 0; mt < 4; ++mt)
        rowA[mt] = (uint32_t)(wm + mt * 16 + (jj & 1) * 8 + rr) * 128;
#pragma unroll
    for (int np = 0; np < 4; ++np)
        rowB[np] = (uint32_t)(wn + np * 16 + (jj >> 1) * 8 + rr) * 128;
    const int cjA = jj >> 1, cjB = jj & 1;

    issue_stage(uA, uB, 0, 0, af, WtD, tid, m0, row_start, n_rows); CP_COMMIT();
    issue_stage(uA, uB, 1, 1, af, WtD, tid, m0, row_start, n_rows); CP_COMMIT();

    for (int kt = 0; kt < 16; ++kt) {
        CP_WAIT1();
        __syncthreads();
        const uint32_t baseA = uA + (uint32_t)(kt & 1) * 16384;
        const uint32_t baseB = uB + (uint32_t)(kt & 1) * 32768;
#pragma unroll
        for (int k8 = 0; k8 < 4; ++k8) {
            uint32_t aF[4][4], bF[4][4];
            const uint32_t ca = (uint32_t)(((2 * k8 + cjA) ^ rr) << 4);
            const uint32_t cb = (uint32_t)(((2 * k8 + cjB) ^ rr) << 4);
#pragma unroll
            for (int mt = 0; mt < 4; ++mt) ldm_x4(aF[mt], baseA + rowA[mt] + ca);
#pragma unroll
            for (int np = 0; np < 4; ++np) ldm_x4(bF[np], baseB + rowB[np] + cb);
#pragma unroll
            for (int mt = 0; mt < 4; ++mt)
#pragma unroll
                for (int np = 0; np < 4; ++np) {
                    mma_tf32(acc[mt][2 * np],     aF[mt], bF[np][0], bF[np][1]);
                    mma_tf32(acc[mt][2 * np + 1], aF[mt], bF[np][2], bF[np][3]);
                }
        }
        __syncthreads();
        if (kt + 2 < 16)
            issue_stage(uA, uB, kt & 1, kt + 2, af, WtD, tid, m0, row_start, n_rows);
        CP_COMMIT();
    }

    // ---- epilogue: + bias + Bsum@wbot, ReLU, store ----
    const int g = lane >> 2, tq = lane & 3;
#pragma unroll
    for (int mt = 0; mt < 4; ++mt) {
#pragma unroll
        for (int half = 0; half < 2; ++half) {
            int r = wm + mt * 16 + g + half * 8;
            if (m0 + r >= n_rows) continue;
            size_t grow = (size_t)(row_start + m0 + r);
            float4 b03 = *(const float4*)(g_Bsum + grow * 8);
            float4 b47 = *(const float4*)(g_Bsum + grow * 8 + 4);
            float bs[6] = {b03.x, b03.y, b03.z, b03.w, b47.x, b47.y};
#pragma unroll
            for (int nt = 0; nt < 8; ++nt) {
                int cl = wn + nt * 8 + tq * 2;
                float v0 = acc[mt][nt][half * 2 + 0] + s_bias[cl];
                float v1 = acc[mt][nt][half * 2 + 1] + s_bias[cl + 1];
#pragma unroll
                for (int j = 0; j < 6; ++j) {
                    v0 = fmaf(bs[j], s_wbot[j][cl],     v0);
                    v1 = fmaf(bs[j], s_wbot[j][cl + 1], v1);
                }
                v0 = fmaxf(v0, 0.f);
                v1 = fmaxf(v1, 0.f);
                *(float2*)(g_pre + grow * 256 + cl) = make_float2(v0, v1);
            }
        }
    }
}

// ---------------------------------------------------------------------------
// 3) batchnorm stats (deterministic, coalesced float4)
// ---------------------------------------------------------------------------
__global__ void __launch_bounds__(256) stats_kernel(int n_atoms)
{
    const int c4 = threadIdx.x & 63;   // float4 column
    const int rl = threadIdx.x >> 6;   // 0..3 row lane
    const int p = blockIdx.x;
    const int chunk = (n_atoms + 255) >> 8;
    int r0 = p * chunk;
    int r1 = r0 + chunk; if (r1 > n_atoms) r1 = n_atoms;

    float4 s  = make_float4(0.f, 0.f, 0.f, 0.f);
    float4 s2 = make_float4(0.f, 0.f, 0.f, 0.f);
    for (int r = r0 + rl; r < r1; r += 4) {
        float4 v = *(const float4*)(g_pre + (size_t)r * 256 + c4 * 4);
        s.x += v.x; s.y += v.y; s.z += v.z; s.w += v.w;
        s2.x = fmaf(v.x, v.x, s2.x); s2.y = fmaf(v.y, v.y, s2.y);
        s2.z = fmaf(v.z, v.z, s2.z); s2.w = fmaf(v.w, v.w, s2.w);
    }
    __shared__ float4 red[2][4][64];
    red[0][rl][c4] = s;
    red[1][rl][c4] = s2;
    __syncthreads();
    if (rl == 0) {
        float4 a = red[0][0][c4], b = red[1][0][c4];
#pragma unroll
        for (int q = 1; q < 4; ++q) {
            float4 x = red[0][q][c4], y = red[1][q][c4];
            a.x += x.x; a.y += x.y; a.z += x.z; a.w += x.w;
            b.x += y.x; b.y += y.y; b.z += y.z; b.w += y.w;
        }
        *(float4*)(g_part + p * 256 + c4 * 4) = a;
        *(float4*)(g_part + 65536 + p * 256 + c4 * 4) = b;
    }
}

__global__ void finalize_kernel(const float* __restrict__ bnw,
                                const float* __restrict__ bnb, int n_atoms)
{
    const int t = threadIdx.x;
    float s = 0.f, s2 = 0.f;
    for (int p = 0; p < 256; ++p) {
        s  += g_part[p * 256 + t];
        s2 += g_part[65536 + p * 256 + t];
    }
    const float inv = 1.f / (float)n_atoms;
    const float mean = s * inv;
    const float var  = s2 * inv - mean * mean;
    const float a = bnw[t] * rsqrtf(var + 1e-5f);
    g_scale[t] = a;
    g_shift[t] = bnb[t] - mean * a;
}

// ---------------------------------------------------------------------------
// 4) normalize
// ---------------------------------------------------------------------------
__global__ void __launch_bounds__(256) norm_kernel(float* __restrict__ out,
                                                   int total4)
{
    __shared__ float sc[256], sh[256];
    sc[threadIdx.x] = g_scale[threadIdx.x];
    sh[threadIdx.x] = g_shift[threadIdx.x];
    __syncthreads();
    for (int i = blockIdx.x * blockDim.x + threadIdx.x; i < total4;
         i += gridDim.x * blockDim.x) {
        float4 v = *(const float4*)(g_pre + (size_t)i * 4);
        int c = (i & 63) * 4;
        v.x = fmaf(v.x, sc[c],     sh[c]);
        v.y = fmaf(v.y, sc[c + 1], sh[c + 1]);
        v.z = fmaf(v.z, sc[c + 2], sh[c + 2]);
        v.w = fmaf(v.w, sc[c + 3], sh[c + 3]);
        *(float4*)(out + (size_t)i * 4) = v;
    }
}

// ---------------------------------------------------------------------------
extern "C" void kernel_launch(void* const* d_in, const int* in_sizes, int n_in,
                              void* d_out, int out_size)
{
    const float* af = (const float*)d_in[0];
    const float* bf = (const float*)d_in[1];

    int a_idx[5], b_idx[5];
    const bool interleaved = (in_sizes[3] == in_sizes[2]);
    for (int d = 0; d < 5; ++d) {
        if (interleaved) { a_idx[d] = 2 + 2 * d; b_idx[d] = 3 + 2 * d; }
        else             { a_idx[d] = 2 + d;     b_idx[d] = 7 + d;     }
    }

    const float* Wself = (const float*)d_in[12];
    const float* bias  = (const float*)d_in[13];
    const float* Wdeg[5];
    for (int d = 0; d < 5; ++d) Wdeg[d] = (const float*)d_in[14 + d];
    const float* bnw = (const float*)d_in[19];
    const float* bnb = (const float*)d_in[20];

    const int n_atoms = in_sizes[0] / 256;

    int nd[5], off[5], o = 0;
    for (int d = 0; d < 5; ++d) {
        nd[d]  = in_sizes[a_idx[d]] / (d + 1);
        off[d] = o;
        o += nd[d];
    }

    cudaFuncSetAttribute(gemm_mma, cudaFuncAttributeMaxDynamicSharedMemorySize,
                         98304);

    // 0) weight prep
    prep_kernel<<<6 * 65536 / 256, 256>>>(Wself, Wdeg[0], Wdeg[1], Wdeg[2],
                                          Wdeg[3], Wdeg[4]);

    // 1) gathers
    for (int d = 0; d < 5; ++d) {
        if (nd[d] <= 0) continue;
        int ga = (nd[d] * 64 + 255) / 256;
        int gb = (nd[d] + 255) / 256;
        const int* an = (const int*)d_in[a_idx[d]];
        const int* bn = (const int*)d_in[b_idx[d]];
        switch (d) {
        case 0: gather_atoms<1><<<ga, 256>>>(af, an, off[d], nd[d]);
                gather_bonds<1><<<gb, 256>>>(bf, bn, off[d], nd[d]); break;
        case 1: gather_atoms<2><<<ga, 256>>>(af, an, off[d], nd[d]);
                gather_bonds<2><<<gb, 256>>>(bf, bn, off[d], nd[d]); break;
        case 2: gather_atoms<3><<<ga, 256>>>(af, an, off[d], nd[d]);
                gather_bonds<3><<<gb, 256>>>(bf, bn, off[d], nd[d]); break;
        case 3: gather_atoms<4><<<ga, 256>>>(af, an, off[d], nd[d]);
                gather_bonds<4><<<gb, 256>>>(bf, bn, off[d], nd[d]); break;
        case 4: gather_atoms<5><<<ga, 256>>>(af, an, off[d], nd[d]);
                gather_bonds<5><<<gb, 256>>>(bf, bn, off[d], nd[d]); break;
        }
    }

    // 2) GEMM per degree segment
    for (int d = 0; d < 5; ++d) {
        if (nd[d] > 0) {
            dim3 grid((nd[d] + 127) / 128);
            gemm_mma<<<grid, 256, 98304>>>(af, Wdeg[d], bias, d, off[d], nd[d]);
        }
    }

    // 3) batchnorm stats
    stats_kernel<<<256, 256>>>(n_atoms);
    finalize_kernel<<<1, 256>>>(bnw, bnb, n_atoms);

    // 4) normalize
    norm_kernel<<<1184, 256>>>((float*)d_out, n_atoms * 64);
}

// round 8
// speedup vs baseline: 2.1720x; 1.1176x over previous
#include <cuda_runtime.h>
#include <cstdint>

// ---------------------------------------------------------------------------
// GraphConvLayer — mma.sync tf32 pipeline, 3-stage cp.async, fused stats
//   0) prep_kernel   : transpose weights -> tf32 [n][k]
//   1) gather_all    : all-degree atom-sum + bond-sum (single launch)
//   2) gemm_mma x5   : 128x256x512, 3-stage cp.async, ldmatrix-b16 tf32,
//                      bias+bond epilogue + ReLU -> g_pre, per-CTA bn stats
//   3) stats_reduce / finalize : deterministic batchnorm scale/shift
//   4) norm_kernel   : g_pre -> d_out
// ---------------------------------------------------------------------------

#define NATOMS_MAX 200000
#define MAX_SLOTS 2048
#define QOFF (MAX_SLOTS * 256)

__device__ float g_Asum[(size_t)NATOMS_MAX * 256];
__device__ float g_Bsum[(size_t)NATOMS_MAX * 8];
__device__ float g_pre [(size_t)NATOMS_MAX * 256];
__device__ float g_Wt_self[256 * 256];        // [n][k], tf32-rounded
__device__ float g_Wt_deg [5 * 256 * 256];    // [d][n][k]
__device__ float g_part [2 * MAX_SLOTS * 256];
__device__ float g_part2[2 * 64 * 256];
__device__ float g_scale[256];
__device__ float g_shift[256];

// ---------------- helpers ----------------
__device__ __forceinline__ uint32_t smem_u32(const void* p) {
    uint32_t a;
    asm("{ .reg .u64 t; cvta.to.shared.u64 t, %1; cvt.u32.u64 %0, t; }"
        : "=r"(a) : "l"(p));
    return a;
}
__device__ __forceinline__ uint32_t f2tf(float f) {
    uint32_t u;
    asm("cvt.rna.tf32.f32 %0, %1;" : "=r"(u) : "f"(f));
    return u;
}
__device__ __forceinline__ void cp_async16(uint32_t saddr, const void* gptr) {
    size_t g = __cvta_generic_to_global(gptr);
    asm volatile("cp.async.cg.shared.global [%0], [%1], 16;"
                 :: "r"(saddr), "l"(g));
}
#define CP_COMMIT() asm volatile("cp.async.commit_group;" ::: "memory")
#define CP_WAIT1()  asm volatile("cp.async.wait_group 1;" ::: "memory")

__device__ __forceinline__ void ldm_x4(uint32_t* r, uint32_t addr) {
    asm volatile("ldmatrix.sync.aligned.m8n8.x4.shared.b16 {%0,%1,%2,%3}, [%4];"
                 : "=r"(r[0]), "=r"(r[1]), "=r"(r[2]), "=r"(r[3]) : "r"(addr));
}
__device__ __forceinline__ void mma_tf32(float* c, const uint32_t* a,
                                         uint32_t b0, uint32_t b1) {
    asm volatile(
        "mma.sync.aligned.m16n8k8.row.col.f32.tf32.tf32.f32 "
        "{%0,%1,%2,%3}, {%4,%5,%6,%7}, {%8,%9}, {%0,%1,%2,%3};"
        : "+f"(c[0]), "+f"(c[1]), "+f"(c[2]), "+f"(c[3])
        : "r"(a[0]), "r"(a[1]), "r"(a[2]), "r"(a[3]), "r"(b0), "r"(b1));
}

// ---------------------------------------------------------------------------
// 0) prep: Wt[n][k] = tf32(W[k][n])
// ---------------------------------------------------------------------------
__global__ void __launch_bounds__(256) prep_kernel(
    const float* __restrict__ Ws,
    const float* __restrict__ W1, const float* __restrict__ W2,
    const float* __restrict__ W3, const float* __restrict__ W4,
    const float* __restrict__ W5)
{
    const float* Wd[5] = {W1, W2, W3, W4, W5};
    int id = blockIdx.x * 256 + threadIdx.x;
    if (id < 65536) {
        int n = id >> 8, k = id & 255;
        g_Wt_self[id] = __uint_as_float(f2tf(__ldg(Ws + k * 256 + n)));
    } else if (id < 6 * 65536) {
        int t = id - 65536;
        int d = t >> 16, rr = t & 65535;
        int n = rr >> 8, k = rr & 255;
        g_Wt_deg[t] = __uint_as_float(f2tf(__ldg(Wd[d] + k * 256 + n)));
    }
}

// ---------------------------------------------------------------------------
// 1) gather (single launch, block-range dispatch over 5+5 segments)
// ---------------------------------------------------------------------------
struct GArgs {
    const int* an[5];
    const int* bn[5];
    int nd[5];
    int off[5];
    int blkA[6];   // cumulative atom-gather blocks
    int blkB[6];   // cumulative bond-gather blocks
};

template <int D>
__device__ __forceinline__ void do_atoms(const float* __restrict__ af,
                                         const int* __restrict__ anbr,
                                         int row_start, int n, int lb)
{
    int gid = lb * 256 + threadIdx.x;
    int atom = gid >> 6;
    if (atom >= n) return;
    int c = gid & 63;
    int idx[D];
#pragma unroll
    for (int s = 0; s < D; ++s) idx[s] = __ldg(anbr + atom * D + s);
    float4 acc = make_float4(0.f, 0.f, 0.f, 0.f);
#pragma unroll
    for (int s = 0; s < D; ++s) {
        float4 v = __ldg((const float4*)af + (size_t)idx[s] * 64 + c);
        acc.x += v.x; acc.y += v.y; acc.z += v.z; acc.w += v.w;
    }
    acc.x = __uint_as_float(f2tf(acc.x));
    acc.y = __uint_as_float(f2tf(acc.y));
    acc.z = __uint_as_float(f2tf(acc.z));
    acc.w = __uint_as_float(f2tf(acc.w));
    ((float4*)g_Asum)[(size_t)(row_start + atom) * 64 + c] = acc;
}

template <int D>
__device__ __forceinline__ void do_bonds(const float* __restrict__ bf,
                                         const int* __restrict__ bnbr,
                                         int row_start, int n, int lb)
{
    int atom = lb * 256 + threadIdx.x;
    if (atom >= n) return;
    float s[6] = {0.f, 0.f, 0.f, 0.f, 0.f, 0.f};
#pragma unroll
    for (int j = 0; j < D; ++j) {
        int idx = __ldg(bnbr + atom * D + j);
        const float* row = bf + (size_t)idx * 6;
#pragma unroll
        for (int q = 0; q < 6; ++q) s[q] += __ldg(row + q);
    }
    float* o = g_Bsum + (size_t)(row_start + atom) * 8;
    *(float4*)o       = make_float4(s[0], s[1], s[2], s[3]);
    *(float4*)(o + 4) = make_float4(s[4], s[5], 0.f, 0.f);
}

__global__ void __launch_bounds__(256) gather_all(
    const float* __restrict__ af, const float* __restrict__ bf, GArgs ga)
{
    int bid = blockIdx.x;
    if (bid < ga.blkA[5]) {
        int d = 0;
        while (bid >= ga.blkA[d + 1]) ++d;
        int lb = bid - ga.blkA[d];
        switch (d) {
        case 0: do_atoms<1>(af, ga.an[0], ga.off[0], ga.nd[0], lb); break;
        case 1: do_atoms<2>(af, ga.an[1], ga.off[1], ga.nd[1], lb); break;
        case 2: do_atoms<3>(af, ga.an[2], ga.off[2], ga.nd[2], lb); break;
        case 3: do_atoms<4>(af, ga.an[3], ga.off[3], ga.nd[3], lb); break;
        default: do_atoms<5>(af, ga.an[4], ga.off[4], ga.nd[4], lb); break;
        }
    } else {
        int bb = bid - ga.blkA[5];
        int d = 0;
        while (bb >= ga.blkB[d + 1]) ++d;
        int lb = bb - ga.blkB[d];
        switch (d) {
        case 0: do_bonds<1>(bf, ga.bn[0], ga.off[0], ga.nd[0], lb); break;
        case 1: do_bonds<2>(bf, ga.bn[1], ga.off[1], ga.nd[1], lb); break;
        case 2: do_bonds<3>(bf, ga.bn[2], ga.off[2], ga.nd[2], lb); break;
        case 3: do_bonds<4>(bf, ga.bn[3], ga.off[3], ga.nd[3], lb); break;
        default: do_bonds<5>(bf, ga.bn[4], ga.off[4], ga.nd[4], lb); break;
        }
    }
}

// ---------------------------------------------------------------------------
// 2) GEMM: CTA 128(M) x 256(N), K=512, 16 stages of 32, 3-slot cp.async.
//    8 warps: 2(M) x 4(N); warp tile 64x64; m16n8k8 tf32 mma (ldmatrix b16).
//    smem slot: A [128][32]f (16KB) @ +slot*16K, B [256][32]f (32KB)
//    @ +49152+slot*32K. SW128 XOR swizzle on 128B rows.
// ---------------------------------------------------------------------------
__device__ __forceinline__ void issue_stage(
    uint32_t uS, int slot, int kt,
    const float* __restrict__ af, const float* __restrict__ WtD,
    int tid, int m0, int row_start, int n_rows)
{
    const int lrow = tid >> 3;
    const int lchk = tid & 7;
    const int kk = (kt * 32) & 255;

    const float* Ab = (kt < 8) ? af : g_Asum;
    uint32_t dA = uS + (uint32_t)slot * 16384;
#pragma unroll
    for (int p = 0; p < 4; ++p) {
        int r = lrow + p * 32;
        int rg = m0 + r; if (rg >= n_rows) rg = n_rows - 1;
        const char* src = (const char*)(Ab + (size_t)(row_start + rg) * 256 + kk)
                          + lchk * 16;
        cp_async16(dA + (uint32_t)r * 128 + (uint32_t)((lchk ^ (r & 7)) << 4), src);
    }
    const float* Bb = (kt < 8) ? g_Wt_self : WtD;
    uint32_t dB = uS + 49152u + (uint32_t)slot * 32768;
#pragma unroll
    for (int p = 0; p < 8; ++p) {
        int r = lrow + p * 32;
        const char* src = (const char*)(Bb + (size_t)r * 256 + kk) + lchk * 16;
        cp_async16(dB + (uint32_t)r * 128 + (uint32_t)((lchk ^ (r & 7)) << 4), src);
    }
}

__global__ void __launch_bounds__(256) gemm_mma(
    const float* __restrict__ af,
    const float* __restrict__ Wdeg_orig,   // original [262][256] for bond rows
    const float* __restrict__ bias,
    int deg, int row_start, int n_rows, int slot_base)
{
    extern __shared__ float dsm[];          // 3 * (16KB A + 32KB B) = 144KB
    __shared__ float s_wbot[6][256];
    __shared__ float s_bias[256];
    __shared__ float s_sum[256];
    __shared__ float s_sq[256];

    const uint32_t uS = smem_u32(dsm);
    const int tid = threadIdx.x;
    const int warp = tid >> 5, lane = tid & 31;
    const int m0 = blockIdx.x * 128;
    const int wm = (warp & 1) * 64;
    const int wn = (warp >> 1) * 64;
    const float* __restrict__ WtD = g_Wt_deg + (size_t)deg * 65536;

    s_bias[tid] = __ldg(bias + tid);
#pragma unroll
    for (int j = 0; j < 6; ++j)
        s_wbot[j][tid] = __ldg(Wdeg_orig + (size_t)(256 + j) * 256 + tid);

    float acc[4][8][4];
#pragma unroll
    for (int a = 0; a < 4; ++a)
#pragma unroll
        for (int b = 0; b < 8; ++b)
#pragma unroll
            for (int e = 0; e < 4; ++e) acc[a][b][e] = 0.f;

    const int jj = lane >> 3, rr = lane & 7;
    uint32_t rowA[4], rowB[4];
#pragma unroll
    for (int mt = 0; mt < 4; ++mt)
        rowA[mt] = (uint32_t)(wm + mt * 16 + (jj & 1) * 8 + rr) * 128;
#pragma unroll
    for (int np = 0; np < 4; ++np)
        rowB[np] = (uint32_t)(wn + np * 16 + (jj >> 1) * 8 + rr) * 128;
    const int cjA = jj >> 1, cjB = jj & 1;

    issue_stage(uS, 0, 0, af, WtD, tid, m0, row_start, n_rows); CP_COMMIT();
    issue_stage(uS, 1, 1, af, WtD, tid, m0, row_start, n_rows); CP_COMMIT();

    int sl = 0, si = 2;
    for (int kt = 0; kt < 16; ++kt) {
        CP_WAIT1();
        __syncthreads();
        if (kt + 2 < 16)
            issue_stage(uS, si, kt + 2, af, WtD, tid, m0, row_start, n_rows);
        CP_COMMIT();

        const uint32_t baseA = uS + (uint32_t)sl * 16384;
        const uint32_t baseB = uS + 49152u + (uint32_t)sl * 32768;
#pragma unroll
        for (int k8 = 0; k8 < 4; ++k8) {
            uint32_t aF[4][4], bF[4][4];
            const uint32_t ca = (uint32_t)(((2 * k8 + cjA) ^ rr) << 4);
            const uint32_t cb = (uint32_t)(((2 * k8 + cjB) ^ rr) << 4);
#pragma unroll
            for (int mt = 0; mt < 4; ++mt) ldm_x4(aF[mt], baseA + rowA[mt] + ca);
#pragma unroll
            for (int np = 0; np < 4; ++np) ldm_x4(bF[np], baseB + rowB[np] + cb);
#pragma unroll
            for (int mt = 0; mt < 4; ++mt)
#pragma unroll
                for (int np = 0; np < 4; ++np) {
                    mma_tf32(acc[mt][2 * np],     aF[mt], bF[np][0], bF[np][1]);
                    mma_tf32(acc[mt][2 * np + 1], aF[mt], bF[np][2], bF[np][3]);
                }
        }
        sl = (sl == 2) ? 0 : sl + 1;
        si = (si == 2) ? 0 : si + 1;
    }

    // ---- epilogue: + bias + Bsum@wbot, ReLU, store, column stats ----
    const int g = lane >> 2, tq = lane & 3;
    float st_s[16], st_q[16];
#pragma unroll
    for (int i = 0; i < 16; ++i) { st_s[i] = 0.f; st_q[i] = 0.f; }

#pragma unroll
    for (int mt = 0; mt < 4; ++mt) {
#pragma unroll
        for (int half = 0; half < 2; ++half) {
            int r = wm + mt * 16 + g + half * 8;
            if (m0 + r >= n_rows) continue;
            size_t grow = (size_t)(row_start + m0 + r);
            float4 b03 = *(const float4*)(g_Bsum + grow * 8);
            float4 b47 = *(const float4*)(g_Bsum + grow * 8 + 4);
            float bs[6] = {b03.x, b03.y, b03.z, b03.w, b47.x, b47.y};
#pragma unroll
            for (int nt = 0; nt < 8; ++nt) {
                int cl = wn + nt * 8 + tq * 2;
                float v0 = acc[mt][nt][half * 2 + 0] + s_bias[cl];
                float v1 = acc[mt][nt][half * 2 + 1] + s_bias[cl + 1];
#pragma unroll
                for (int j = 0; j < 6; ++j) {
                    v0 = fmaf(bs[j], s_wbot[j][cl],     v0);
                    v1 = fmaf(bs[j], s_wbot[j][cl + 1], v1);
                }
                v0 = fmaxf(v0, 0.f);
                v1 = fmaxf(v1, 0.f);
                *(float2*)(g_pre + grow * 256 + cl) = make_float2(v0, v1);
                st_s[nt * 2]     += v0;
                st_s[nt * 2 + 1] += v1;
                st_q[nt * 2]     = fmaf(v0, v0, st_q[nt * 2]);
                st_q[nt * 2 + 1] = fmaf(v1, v1, st_q[nt * 2 + 1]);
            }
        }
    }
    // reduce over the 8 row-lanes (g): lanes differing in bits 2..4
#pragma unroll
    for (int off = 4; off < 32; off <<= 1) {
#pragma unroll
        for (int i = 0; i < 16; ++i) {
            st_s[i] += __shfl_xor_sync(0xffffffffu, st_s[i], off);
            st_q[i] += __shfl_xor_sync(0xffffffffu, st_q[i], off);
        }
    }
    __syncthreads();               // dsm no longer needed; order stats phases
    if ((warp & 1) == 0 && lane < 4) {
#pragma unroll
        for (int nt = 0; nt < 8; ++nt) {
            int cl = wn + nt * 8 + lane * 2;
            s_sum[cl]     = st_s[nt * 2];
            s_sum[cl + 1] = st_s[nt * 2 + 1];
            s_sq[cl]      = st_q[nt * 2];
            s_sq[cl + 1]  = st_q[nt * 2 + 1];
        }
    }
    __syncthreads();
    if ((warp & 1) == 1 && lane < 4) {
#pragma unroll
        for (int nt = 0; nt < 8; ++nt) {
            int cl = wn + nt * 8 + lane * 2;
            s_sum[cl]     += st_s[nt * 2];
            s_sum[cl + 1] += st_s[nt * 2 + 1];
            s_sq[cl]      += st_q[nt * 2];
            s_sq[cl + 1]  += st_q[nt * 2 + 1];
        }
    }
    __syncthreads();
    const int slot = slot_base + blockIdx.x;
    g_part[slot * 256 + tid]        = s_sum[tid];
    g_part[QOFF + slot * 256 + tid] = s_sq[tid];
}

// ---------------------------------------------------------------------------
// 3) stats reduction (deterministic)
// ---------------------------------------------------------------------------
__global__ void __launch_bounds__(256) stats_reduce(int n_slots)
{
    const int b = blockIdx.x, t = threadIdx.x;
    const int chunk = (n_slots + 63) >> 6;
    int p0 = b * chunk;
    int p1 = p0 + chunk; if (p1 > n_slots) p1 = n_slots;
    float s = 0.f, q = 0.f;
    for (int p = p0; p < p1; ++p) {
        s += g_part[p * 256 + t];
        q += g_part[QOFF + p * 256 + t];
    }
    g_part2[b * 256 + t] = s;
    g_part2[64 * 256 + b * 256 + t] = q;
}

__global__ void finalize_kernel(const float* __restrict__ bnw,
                                const float* __restrict__ bnb, int n_atoms)
{
    const int t = threadIdx.x;
    float s = 0.f, q = 0.f;
    for (int p = 0; p < 64; ++p) {
        s += g_part2[p * 256 + t];
        q += g_part2[64 * 256 + p * 256 + t];
    }
    const float inv = 1.f / (float)n_atoms;
    const float mean = s * inv;
    const float var  = q * inv - mean * mean;
    const float a = bnw[t] * rsqrtf(var + 1e-5f);
    g_scale[t] = a;
    g_shift[t] = bnb[t] - mean * a;
}

// ---------------------------------------------------------------------------
// 4) normalize
// ---------------------------------------------------------------------------
__global__ void __launch_bounds__(256) norm_kernel(float* __restrict__ out,
                                                   int total4)
{
    __shared__ float sc[256], sh[256];
    sc[threadIdx.x] = g_scale[threadIdx.x];
    sh[threadIdx.x] = g_shift[threadIdx.x];
    __syncthreads();
    for (int i = blockIdx.x * blockDim.x + threadIdx.x; i < total4;
         i += gridDim.x * blockDim.x) {
        float4 v = *(const float4*)(g_pre + (size_t)i * 4);
        int c = (i & 63) * 4;
        v.x = fmaf(v.x, sc[c],     sh[c]);
        v.y = fmaf(v.y, sc[c + 1], sh[c + 1]);
        v.z = fmaf(v.z, sc[c + 2], sh[c + 2]);
        v.w = fmaf(v.w, sc[c + 3], sh[c + 3]);
        *(float4*)(out + (size_t)i * 4) = v;
    }
}

// ---------------------------------------------------------------------------
extern "C" void kernel_launch(void* const* d_in, const int* in_sizes, int n_in,
                              void* d_out, int out_size)
{
    const float* af = (const float*)d_in[0];
    const float* bf = (const float*)d_in[1];

    int a_idx[5], b_idx[5];
    const bool interleaved = (in_sizes[3] == in_sizes[2]);
    for (int d = 0; d < 5; ++d) {
        if (interleaved) { a_idx[d] = 2 + 2 * d; b_idx[d] = 3 + 2 * d; }
        else             { a_idx[d] = 2 + d;     b_idx[d] = 7 + d;     }
    }

    const float* Wself = (const float*)d_in[12];
    const float* bias  = (const float*)d_in[13];
    const float* Wdeg[5];
    for (int d = 0; d < 5; ++d) Wdeg[d] = (const float*)d_in[14 + d];
    const float* bnw = (const float*)d_in[19];
    const float* bnb = (const float*)d_in[20];

    const int n_atoms = in_sizes[0] / 256;

    GArgs ga;
    int o = 0;
    ga.blkA[0] = 0; ga.blkB[0] = 0;
    for (int d = 0; d < 5; ++d) {
        ga.an[d]  = (const int*)d_in[a_idx[d]];
        ga.bn[d]  = (const int*)d_in[b_idx[d]];
        ga.nd[d]  = in_sizes[a_idx[d]] / (d + 1);
        ga.off[d] = o;
        o += ga.nd[d];
        ga.blkA[d + 1] = ga.blkA[d] + (ga.nd[d] + 3) / 4;       // 64 thr/atom
        ga.blkB[d + 1] = ga.blkB[d] + (ga.nd[d] + 255) / 256;
    }

    cudaFuncSetAttribute(gemm_mma, cudaFuncAttributeMaxDynamicSharedMemorySize,
                         147456);

    // 0) weight prep
    prep_kernel<<<6 * 65536 / 256, 256>>>(Wself, Wdeg[0], Wdeg[1], Wdeg[2],
                                          Wdeg[3], Wdeg[4]);

    // 1) all gathers in one launch
    gather_all<<<ga.blkA[5] + ga.blkB[5], 256>>>(af, bf, ga);

    // 2) GEMM per degree segment (with fused per-CTA bn stats)
    int slot_base = 0;
    for (int d = 0; d < 5; ++d) {
        if (ga.nd[d] > 0) {
            int nblk = (ga.nd[d] + 127) / 128;
            gemm_mma<<<nblk, 256, 147456>>>(af, Wdeg[d], bias, d,
                                            ga.off[d], ga.nd[d], slot_base);
            slot_base += nblk;
        }
    }

    // 3) batchnorm stats reduction
    stats_reduce<<<64, 256>>>(slot_base);
    finalize_kernel<<<1, 256>>>(bnw, bnb, n_atoms);

    // 4) normalize
    norm_kernel<<<1184, 256>>>((float*)d_out, n_atoms * 64);
}

// round 9
// speedup vs baseline: 2.6442x; 1.2174x over previous
#include <cuda_runtime.h>
#include <cstdint>

// ---------------------------------------------------------------------------
// GraphConvLayer — mma.sync tf32, 4-deep cp.async, frag ping-pong, merged grid
//   0) prep_kernel   : transpose weights -> tf32 [n][k]
//   1) gather_all    : all-degree atom-sum + bond-sum (single launch)
//   2) gemm_mma      : ONE launch, 1565 CTAs over 5 segments; 128x256x512,
//                      4-slot cp.async (distance 3), ldmatrix ping-pong,
//                      bias+bond epilogue + ReLU -> g_pre, per-CTA bn stats
//   3) stats_reduce / finalize : deterministic batchnorm scale/shift
//   4) norm_kernel   : g_pre -> d_out
// ---------------------------------------------------------------------------

#define NATOMS_MAX 200000
#define MAX_SLOTS 2048
#define QOFF (MAX_SLOTS * 256)

__device__ float g_Asum[(size_t)NATOMS_MAX * 256];
__device__ float g_Bsum[(size_t)NATOMS_MAX * 8];
__device__ float g_pre [(size_t)NATOMS_MAX * 256];
__device__ float g_Wt_self[256 * 256];        // [n][k], tf32-rounded
__device__ float g_Wt_deg [5 * 256 * 256];    // [d][n][k]
__device__ float g_part [2 * MAX_SLOTS * 256];
__device__ float g_part2[2 * 64 * 256];
__device__ float g_scale[256];
__device__ float g_shift[256];

// ---------------- helpers ----------------
__device__ __forceinline__ uint32_t smem_u32(const void* p) {
    uint32_t a;
    asm("{ .reg .u64 t; cvta.to.shared.u64 t, %1; cvt.u32.u64 %0, t; }"
        : "=r"(a) : "l"(p));
    return a;
}
__device__ __forceinline__ uint32_t f2tf(float f) {
    uint32_t u;
    asm("cvt.rna.tf32.f32 %0, %1;" : "=r"(u) : "f"(f));
    return u;
}
__device__ __forceinline__ void cp_async16(uint32_t saddr, const void* gptr) {
    size_t g = __cvta_generic_to_global(gptr);
    asm volatile("cp.async.cg.shared.global [%0], [%1], 16;"
                 :: "r"(saddr), "l"(g));
}
#define CP_COMMIT() asm volatile("cp.async.commit_group;" ::: "memory")
#define CP_WAIT2()  asm volatile("cp.async.wait_group 2;" ::: "memory")

__device__ __forceinline__ void ldm_x4(uint32_t* r, uint32_t addr) {
    asm volatile("ldmatrix.sync.aligned.m8n8.x4.shared.b16 {%0,%1,%2,%3}, [%4];"
                 : "=r"(r[0]), "=r"(r[1]), "=r"(r[2]), "=r"(r[3]) : "r"(addr));
}
__device__ __forceinline__ void mma_tf32(float* c, const uint32_t* a,
                                         uint32_t b0, uint32_t b1) {
    asm volatile(
        "mma.sync.aligned.m16n8k8.row.col.f32.tf32.tf32.f32 "
        "{%0,%1,%2,%3}, {%4,%5,%6,%7}, {%8,%9}, {%0,%1,%2,%3};"
        : "+f"(c[0]), "+f"(c[1]), "+f"(c[2]), "+f"(c[3])
        : "r"(a[0]), "r"(a[1]), "r"(a[2]), "r"(a[3]), "r"(b0), "r"(b1));
}

// ---------------------------------------------------------------------------
// 0) prep: Wt[n][k] = tf32(W[k][n])
// ---------------------------------------------------------------------------
__global__ void __launch_bounds__(256) prep_kernel(
    const float* __restrict__ Ws,
    const float* __restrict__ W1, const float* __restrict__ W2,
    const float* __restrict__ W3, const float* __restrict__ W4,
    const float* __restrict__ W5)
{
    const float* Wd[5] = {W1, W2, W3, W4, W5};
    int id = blockIdx.x * 256 + threadIdx.x;
    if (id < 65536) {
        int n = id >> 8, k = id & 255;
        g_Wt_self[id] = __uint_as_float(f2tf(__ldg(Ws + k * 256 + n)));
    } else if (id < 6 * 65536) {
        int t = id - 65536;
        int d = t >> 16, rr = t & 65535;
        int n = rr >> 8, k = rr & 255;
        g_Wt_deg[t] = __uint_as_float(f2tf(__ldg(Wd[d] + k * 256 + n)));
    }
}

// ---------------------------------------------------------------------------
// 1) gather (single launch, block-range dispatch over 5+5 segments)
// ---------------------------------------------------------------------------
struct GArgs {
    const int* an[5];
    const int* bn[5];
    int nd[5];
    int off[5];
    int blkA[6];
    int blkB[6];
};

template <int D>
__device__ __forceinline__ void do_atoms(const float* __restrict__ af,
                                         const int* __restrict__ anbr,
                                         int row_start, int n, int lb)
{
    int gid = lb * 256 + threadIdx.x;
    int atom = gid >> 6;
    if (atom >= n) return;
    int c = gid & 63;
    int idx[D];
#pragma unroll
    for (int s = 0; s < D; ++s) idx[s] = __ldg(anbr + atom * D + s);
    float4 acc = make_float4(0.f, 0.f, 0.f, 0.f);
#pragma unroll
    for (int s = 0; s < D; ++s) {
        float4 v = __ldg((const float4*)af + (size_t)idx[s] * 64 + c);
        acc.x += v.x; acc.y += v.y; acc.z += v.z; acc.w += v.w;
    }
    acc.x = __uint_as_float(f2tf(acc.x));
    acc.y = __uint_as_float(f2tf(acc.y));
    acc.z = __uint_as_float(f2tf(acc.z));
    acc.w = __uint_as_float(f2tf(acc.w));
    ((float4*)g_Asum)[(size_t)(row_start + atom) * 64 + c] = acc;
}

template <int D>
__device__ __forceinline__ void do_bonds(const float* __restrict__ bf,
                                         const int* __restrict__ bnbr,
                                         int row_start, int n, int lb)
{
    int atom = lb * 256 + threadIdx.x;
    if (atom >= n) return;
    float s[6] = {0.f, 0.f, 0.f, 0.f, 0.f, 0.f};
#pragma unroll
    for (int j = 0; j < D; ++j) {
        int idx = __ldg(bnbr + atom * D + j);
        const float* row = bf + (size_t)idx * 6;
#pragma unroll
        for (int q = 0; q < 6; ++q) s[q] += __ldg(row + q);
    }
    float* o = g_Bsum + (size_t)(row_start + atom) * 8;
    *(float4*)o       = make_float4(s[0], s[1], s[2], s[3]);
    *(float4*)(o + 4) = make_float4(s[4], s[5], 0.f, 0.f);
}

__global__ void __launch_bounds__(256) gather_all(
    const float* __restrict__ af, const float* __restrict__ bf, GArgs ga)
{
    int bid = blockIdx.x;
    if (bid < ga.blkA[5]) {
        int d = 0;
        while (bid >= ga.blkA[d + 1]) ++d;
        int lb = bid - ga.blkA[d];
        switch (d) {
        case 0: do_atoms<1>(af, ga.an[0], ga.off[0], ga.nd[0], lb); break;
        case 1: do_atoms<2>(af, ga.an[1], ga.off[1], ga.nd[1], lb); break;
        case 2: do_atoms<3>(af, ga.an[2], ga.off[2], ga.nd[2], lb); break;
        case 3: do_atoms<4>(af, ga.an[3], ga.off[3], ga.nd[3], lb); break;
        default: do_atoms<5>(af, ga.an[4], ga.off[4], ga.nd[4], lb); break;
        }
    } else {
        int bb = bid - ga.blkA[5];
        int d = 0;
        while (bb >= ga.blkB[d + 1]) ++d;
        int lb = bb - ga.blkB[d];
        switch (d) {
        case 0: do_bonds<1>(bf, ga.bn[0], ga.off[0], ga.nd[0], lb); break;
        case 1: do_bonds<2>(bf, ga.bn[1], ga.off[1], ga.nd[1], lb); break;
        case 2: do_bonds<3>(bf, ga.bn[2], ga.off[2], ga.nd[2], lb); break;
        case 3: do_bonds<4>(bf, ga.bn[3], ga.off[3], ga.nd[3], lb); break;
        default: do_bonds<5>(bf, ga.bn[4], ga.off[4], ga.nd[4], lb); break;
        }
    }
}

// ---------------------------------------------------------------------------
// 2) merged GEMM: one launch over all 5 segments.
//    CTA 128(M) x 256(N), K=512, 16 stages of 32, 4-slot cp.async (dist 3).
//    8 warps: 2(M) x 4(N); warp tile 64x64; ldmatrix-b16 tf32 frag ping-pong.
//    smem: A slots 4x16KB @ uS, B slots 4x32KB @ uS+65536 (192KB total).
// ---------------------------------------------------------------------------
struct SegArgs {
    const float* Worig[5];   // original [262][256] (bond rows + dispatch)
    int blk[6];              // cumulative CTA offsets per segment
    int off[5];
    int nd[5];
};

__device__ __forceinline__ void issue_stage(
    uint32_t uS, int slot, int kt,
    const float* __restrict__ af, const float* __restrict__ WtD,
    int tid, int m0, int row_start, int n_rows)
{
    const int lrow = tid >> 3;
    const int lchk = tid & 7;
    const int kk = (kt * 32) & 255;

    const float* Ab = (kt < 8) ? af : g_Asum;
    uint32_t dA = uS + (uint32_t)slot * 16384;
#pragma unroll
    for (int p = 0; p < 4; ++p) {
        int r = lrow + p * 32;
        int rg = m0 + r; if (rg >= n_rows) rg = n_rows - 1;
        const char* src = (const char*)(Ab + (size_t)(row_start + rg) * 256 + kk)
                          + lchk * 16;
        cp_async16(dA + (uint32_t)r * 128 + (uint32_t)((lchk ^ (r & 7)) << 4), src);
    }
    const float* Bb = (kt < 8) ? g_Wt_self : WtD;
    uint32_t dB = uS + 65536u + (uint32_t)slot * 32768;
#pragma unroll
    for (int p = 0; p < 8; ++p) {
        int r = lrow + p * 32;
        const char* src = (const char*)(Bb + (size_t)r * 256 + kk) + lchk * 16;
        cp_async16(dB + (uint32_t)r * 128 + (uint32_t)((lchk ^ (r & 7)) << 4), src);
    }
}

__global__ void __launch_bounds__(256, 1) gemm_mma(
    const float* __restrict__ af, const float* __restrict__ bias, SegArgs sa)
{
    extern __shared__ float dsm[];          // 4*(16KB A) + 4*(32KB B) = 192KB
    __shared__ float s_wbot[6][256];
    __shared__ float s_bias[256];
    __shared__ float s_sum[256];
    __shared__ float s_sq[256];

    // ---- segment dispatch ----
    int deg = 0;
    while ((int)blockIdx.x >= sa.blk[deg + 1]) ++deg;
    const int m0 = (blockIdx.x - sa.blk[deg]) * 128;
    const int row_start = sa.off[deg];
    const int n_rows = sa.nd[deg];
    const float* __restrict__ Worig = sa.Worig[deg];
    const float* __restrict__ WtD = g_Wt_deg + (size_t)deg * 65536;

    const uint32_t uS = smem_u32(dsm);
    const int tid = threadIdx.x;
    const int warp = tid >> 5, lane = tid & 31;
    const int wm = (warp & 1) * 64;
    const int wn = (warp >> 1) * 64;

    s_bias[tid] = __ldg(bias + tid);
#pragma unroll
    for (int j = 0; j < 6; ++j)
        s_wbot[j][tid] = __ldg(Worig + (size_t)(256 + j) * 256 + tid);

    float acc[4][8][4];
#pragma unroll
    for (int a = 0; a < 4; ++a)
#pragma unroll
        for (int b = 0; b < 8; ++b)
#pragma unroll
            for (int e = 0; e < 4; ++e) acc[a][b][e] = 0.f;

    const int jj = lane >> 3, rr = lane & 7;
    uint32_t rowA[4], rowB[4];
#pragma unroll
    for (int mt = 0; mt < 4; ++mt)
        rowA[mt] = (uint32_t)(wm + mt * 16 + (jj & 1) * 8 + rr) * 128;
#pragma unroll
    for (int np = 0; np < 4; ++np)
        rowB[np] = (uint32_t)(wn + np * 16 + (jj >> 1) * 8 + rr) * 128;
    const int cjA = jj >> 1, cjB = jj & 1;

    issue_stage(uS, 0, 0, af, WtD, tid, m0, row_start, n_rows); CP_COMMIT();
    issue_stage(uS, 1, 1, af, WtD, tid, m0, row_start, n_rows); CP_COMMIT();
    issue_stage(uS, 2, 2, af, WtD, tid, m0, row_start, n_rows); CP_COMMIT();

    uint32_t aF[2][4][4], bF[2][4][4];

#define LOAD_FRAGS(buf, k8, bA, bB) do {                                      \
    const uint32_t ca_ = (uint32_t)(((2 * (k8) + cjA) ^ rr) << 4);            \
    const uint32_t cb_ = (uint32_t)(((2 * (k8) + cjB) ^ rr) << 4);            \
    _Pragma("unroll")                                                         \
    for (int mt_ = 0; mt_ < 4; ++mt_) ldm_x4(aF[buf][mt_], (bA) + rowA[mt_] + ca_); \
    _Pragma("unroll")                                                         \
    for (int np_ = 0; np_ < 4; ++np_) ldm_x4(bF[buf][np_], (bB) + rowB[np_] + cb_); \
} while (0)

    for (int kt = 0; kt < 16; ++kt) {
        CP_WAIT2();
        __syncthreads();
        if (kt + 3 < 16)
            issue_stage(uS, (kt + 3) & 3, kt + 3, af, WtD, tid, m0, row_start, n_rows);
        CP_COMMIT();

        const uint32_t baseA = uS + (uint32_t)(kt & 3) * 16384;
        const uint32_t baseB = uS + 65536u + (uint32_t)(kt & 3) * 32768;

        LOAD_FRAGS(0, 0, baseA, baseB);
#pragma unroll
        for (int k8 = 0; k8 < 4; ++k8) {
            const int cur = k8 & 1;
            if (k8 < 3) LOAD_FRAGS(cur ^ 1, k8 + 1, baseA, baseB);
#pragma unroll
            for (int mt = 0; mt < 4; ++mt)
#pragma unroll
                for (int np = 0; np < 4; ++np) {
                    mma_tf32(acc[mt][2 * np],     aF[cur][mt], bF[cur][np][0], bF[cur][np][1]);
                    mma_tf32(acc[mt][2 * np + 1], aF[cur][mt], bF[cur][np][2], bF[cur][np][3]);
                }
        }
    }
#undef LOAD_FRAGS

    // ---- epilogue: + bias + Bsum@wbot, ReLU, store, column stats ----
    const int g = lane >> 2, tq = lane & 3;
    float st_s[16], st_q[16];
#pragma unroll
    for (int i = 0; i < 16; ++i) { st_s[i] = 0.f; st_q[i] = 0.f; }

#pragma unroll
    for (int mt = 0; mt < 4; ++mt) {
#pragma unroll
        for (int half = 0; half < 2; ++half) {
            int r = wm + mt * 16 + g + half * 8;
            if (m0 + r >= n_rows) continue;
            size_t grow = (size_t)(row_start + m0 + r);
            float4 b03 = *(const float4*)(g_Bsum + grow * 8);
            float4 b47 = *(const float4*)(g_Bsum + grow * 8 + 4);
            float bs[6] = {b03.x, b03.y, b03.z, b03.w, b47.x, b47.y};
#pragma unroll
            for (int nt = 0; nt < 8; ++nt) {
                int cl = wn + nt * 8 + tq * 2;
                float v0 = acc[mt][nt][half * 2 + 0] + s_bias[cl];
                float v1 = acc[mt][nt][half * 2 + 1] + s_bias[cl + 1];
#pragma unroll
                for (int j = 0; j < 6; ++j) {
                    v0 = fmaf(bs[j], s_wbot[j][cl],     v0);
                    v1 = fmaf(bs[j], s_wbot[j][cl + 1], v1);
                }
                v0 = fmaxf(v0, 0.f);
                v1 = fmaxf(v1, 0.f);
                *(float2*)(g_pre + grow * 256 + cl) = make_float2(v0, v1);
                st_s[nt * 2]     += v0;
                st_s[nt * 2 + 1] += v1;
                st_q[nt * 2]     = fmaf(v0, v0, st_q[nt * 2]);
                st_q[nt * 2 + 1] = fmaf(v1, v1, st_q[nt * 2 + 1]);
            }
        }
    }
#pragma unroll
    for (int off = 4; off < 32; off <<= 1) {
#pragma unroll
        for (int i = 0; i < 16; ++i) {
            st_s[i] += __shfl_xor_sync(0xffffffffu, st_s[i], off);
            st_q[i] += __shfl_xor_sync(0xffffffffu, st_q[i], off);
        }
    }
    __syncthreads();
    if ((warp & 1) == 0 && lane < 4) {
#pragma unroll
        for (int nt = 0; nt < 8; ++nt) {
            int cl = wn + nt * 8 + lane * 2;
            s_sum[cl]     = st_s[nt * 2];
            s_sum[cl + 1] = st_s[nt * 2 + 1];
            s_sq[cl]      = st_q[nt * 2];
            s_sq[cl + 1]  = st_q[nt * 2 + 1];
        }
    }
    __syncthreads();
    if ((warp & 1) == 1 && lane < 4) {
#pragma unroll
        for (int nt = 0; nt < 8; ++nt) {
            int cl = wn + nt * 8 + lane * 2;
            s_sum[cl]     += st_s[nt * 2];
            s_sum[cl + 1] += st_s[nt * 2 + 1];
            s_sq[cl]      += st_q[nt * 2];
            s_sq[cl + 1]  += st_q[nt * 2 + 1];
        }
    }
    __syncthreads();
    g_part[blockIdx.x * 256 + tid]        = s_sum[tid];
    g_part[QOFF + blockIdx.x * 256 + tid] = s_sq[tid];
}

// ---------------------------------------------------------------------------
// 3) stats reduction (deterministic)
// ---------------------------------------------------------------------------
__global__ void __launch_bounds__(256) stats_reduce(int n_slots)
{
    const int b = blockIdx.x, t = threadIdx.x;
    const int chunk = (n_slots + 63) >> 6;
    int p0 = b * chunk;
    int p1 = p0 + chunk; if (p1 > n_slots) p1 = n_slots;
    float s = 0.f, q = 0.f;
    for (int p = p0; p < p1; ++p) {
        s += g_part[p * 256 + t];
        q += g_part[QOFF + p * 256 + t];
    }
    g_part2[b * 256 + t] = s;
    g_part2[64 * 256 + b * 256 + t] = q;
}

__global__ void finalize_kernel(const float* __restrict__ bnw,
                                const float* __restrict__ bnb, int n_atoms)
{
    const int t = threadIdx.x;
    float s = 0.f, q = 0.f;
    for (int p = 0; p < 64; ++p) {
        s += g_part2[p * 256 + t];
        q += g_part2[64 * 256 + p * 256 + t];
    }
    const float inv = 1.f / (float)n_atoms;
    const float mean = s * inv;
    const float var  = q * inv - mean * mean;
    const float a = bnw[t] * rsqrtf(var + 1e-5f);
    g_scale[t] = a;
    g_shift[t] = bnb[t] - mean * a;
}

// ---------------------------------------------------------------------------
// 4) normalize
// ---------------------------------------------------------------------------
__global__ void __launch_bounds__(256) norm_kernel(float* __restrict__ out,
                                                   int total4)
{
    __shared__ float sc[256], sh[256];
    sc[threadIdx.x] = g_scale[threadIdx.x];
    sh[threadIdx.x] = g_shift[threadIdx.x];
    __syncthreads();
    for (int i = blockIdx.x * blockDim.x + threadIdx.x; i < total4;
         i += gridDim.x * blockDim.x) {
        float4 v = *(const float4*)(g_pre + (size_t)i * 4);
        int c = (i & 63) * 4;
        v.x = fmaf(v.x, sc[c],     sh[c]);
        v.y = fmaf(v.y, sc[c + 1], sh[c + 1]);
        v.z = fmaf(v.z, sc[c + 2], sh[c + 2]);
        v.w = fmaf(v.w, sc[c + 3], sh[c + 3]);
        *(float4*)(out + (size_t)i * 4) = v;
    }
}

// ---------------------------------------------------------------------------
extern "C" void kernel_launch(void* const* d_in, const int* in_sizes, int n_in,
                              void* d_out, int out_size)
{
    const float* af = (const float*)d_in[0];
    const float* bf = (const float*)d_in[1];

    int a_idx[5], b_idx[5];
    const bool interleaved = (in_sizes[3] == in_sizes[2]);
    for (int d = 0; d < 5; ++d) {
        if (interleaved) { a_idx[d] = 2 + 2 * d; b_idx[d] = 3 + 2 * d; }
        else             { a_idx[d] = 2 + d;     b_idx[d] = 7 + d;     }
    }

    const float* Wself = (const float*)d_in[12];
    const float* bias  = (const float*)d_in[13];
    const float* Wdeg[5];
    for (int d = 0; d < 5; ++d) Wdeg[d] = (const float*)d_in[14 + d];
    const float* bnw = (const float*)d_in[19];
    const float* bnb = (const float*)d_in[20];

    const int n_atoms = in_sizes[0] / 256;

    GArgs ga;
    SegArgs sa;
    int o = 0;
    ga.blkA[0] = 0; ga.blkB[0] = 0; sa.blk[0] = 0;
    for (int d = 0; d < 5; ++d) {
        ga.an[d]  = (const int*)d_in[a_idx[d]];
        ga.bn[d]  = (const int*)d_in[b_idx[d]];
        ga.nd[d]  = in_sizes[a_idx[d]] / (d + 1);
        ga.off[d] = o;
        sa.Worig[d] = Wdeg[d];
        sa.nd[d]  = ga.nd[d];
        sa.off[d] = o;
        o += ga.nd[d];
        ga.blkA[d + 1] = ga.blkA[d] + (ga.nd[d] + 3) / 4;
        ga.blkB[d + 1] = ga.blkB[d] + (ga.nd[d] + 255) / 256;
        sa.blk[d + 1]  = sa.blk[d] + (ga.nd[d] + 127) / 128;
    }

    cudaFuncSetAttribute(gemm_mma, cudaFuncAttributeMaxDynamicSharedMemorySize,
                         196608);

    // 0) weight prep
    prep_kernel<<<6 * 65536 / 256, 256>>>(Wself, Wdeg[0], Wdeg[1], Wdeg[2],
                                          Wdeg[3], Wdeg[4]);

    // 1) all gathers in one launch
    gather_all<<<ga.blkA[5] + ga.blkB[5], 256>>>(af, bf, ga);

    // 2) merged GEMM (with fused per-CTA bn stats)
    gemm_mma<<<sa.blk[5], 256, 196608>>>(af, bias, sa);

    // 3) batchnorm stats reduction
    stats_reduce<<<64, 256>>>(sa.blk[5]);
    finalize_kernel<<<1, 256>>>(bnw, bnb, n_atoms);

    // 4) normalize
    norm_kernel<<<1184, 256>>>((float*)d_out, n_atoms * 64);
}